// round 2
// baseline (speedup 1.0000x reference)
#include <cuda_runtime.h>
#include <cstdint>

#define BATCH    8192
#define N_IN     4096
#define N_NODES  2048
#define FAN_IN   8
#define TB       4                 // batch rows per block (SMEM tile)
#define THREADS  256
#define ROW_STRIDE (N_IN + 1)      // 4097 floats -> bank = (b + col) % 32

// Packed node table: per node 8 pairs (w2, idx_bits) interleaved = 16 floats.
// w2 = (w - logsumexp(w)) * log2(e); idx stored as int bits in a float slot.
__device__ float g_node[N_NODES * 16];

__device__ __forceinline__ float ex2f(float x) {
    float r; asm("ex2.approx.f32 %0, %1;" : "=f"(r) : "f"(x)); return r;
}
__device__ __forceinline__ float lg2f(float x) {
    float r; asm("lg2.approx.f32 %0, %1;" : "=f"(r) : "f"(x)); return r;
}

// ---------------------------------------------------------------------------
// Prep: fold log_softmax normalizer into weights; idx arrives as int32
// (the harness downcasts the reference's int64 index array).
// ---------------------------------------------------------------------------
__global__ void prep_kernel(const float* __restrict__ w,
                            const int* __restrict__ idxs) {
    int n = blockIdx.x * blockDim.x + threadIdx.x;
    if (n >= N_NODES) return;
    float wv[FAN_IN];
    float m = -1e30f;
#pragma unroll
    for (int k = 0; k < FAN_IN; k++) {
        wv[k] = w[n * FAN_IN + k];
        m = fmaxf(m, wv[k]);
    }
    float s = 0.0f;
#pragma unroll
    for (int k = 0; k < FAN_IN; k++) s += ex2f((wv[k] - m) * 1.4426950408889634f);
    float lsew = m + lg2f(s) * 0.69314718055994531f;
#pragma unroll
    for (int k = 0; k < FAN_IN; k++) {
        g_node[n * 16 + 2 * k]     = (wv[k] - lsew) * 1.4426950408889634f;
        g_node[n * 16 + 2 * k + 1] = __int_as_float(idxs[n * FAN_IN + k]);
    }
}

// ---------------------------------------------------------------------------
// Main: each block owns TB=4 batch rows staged in SMEM (pre-scaled by log2e).
// Warp lane map: b = lane&3 (4 batch rows), node = chunk*64 + warp*8 + (lane>>2).
//  - Gather LDS: per column, 4 lanes hit 4 consecutive banks (stride 4097).
//  - Node table read as 4x float4, same address across 4 lanes (coalesced/bcast).
//  - Output: 4 x 32B fully-utilized sectors per warp store.
// ---------------------------------------------------------------------------
__global__ void __launch_bounds__(THREADS)
sum_layer_kernel(const float* __restrict__ x, float* __restrict__ out) {
    extern __shared__ float xs[];            // [TB][ROW_STRIDE]
    const int tid = threadIdx.x;
    const int b0  = blockIdx.x * TB;

    // Stage TB contiguous rows of x (they are contiguous in memory), * log2e.
    const float4* xv = (const float4*)(x + (size_t)b0 * N_IN);
    const float LOG2E = 1.4426950408889634f;
    for (int v = tid; v < TB * (N_IN / 4); v += THREADS) {
        int r  = v >> 10;                    // N_IN/4 == 1024
        int c4 = v & 1023;
        float4 f = xv[v];
        float* d = xs + r * ROW_STRIDE + c4 * 4;
        d[0] = f.x * LOG2E; d[1] = f.y * LOG2E;
        d[2] = f.z * LOG2E; d[3] = f.w * LOG2E;
    }
    __syncthreads();

    const int b  = tid & 3;
    const int nl = (tid >> 2) & 7;
    const int w  = tid >> 5;

    const float4* nd   = (const float4*)g_node;
    const float* xrow  = xs + b * ROW_STRIDE;
    float* outrow      = out + (size_t)(b0 + b) * N_NODES;

#pragma unroll 4
    for (int chunk = 0; chunk < N_NODES / 64; chunk++) {
        int n = chunk * 64 + w * 8 + nl;
        // 4 independent 16B loads up-front (MLP), L1/L2-resident table.
        float4 p0 = __ldg(&nd[n * 4 + 0]);
        float4 p1 = __ldg(&nd[n * 4 + 1]);
        float4 p2 = __ldg(&nd[n * 4 + 2]);
        float4 p3 = __ldg(&nd[n * 4 + 3]);

        float s0, s1;
        s0  = ex2f(xrow[__float_as_int(p0.y)] + p0.x);
        s1  = ex2f(xrow[__float_as_int(p0.w)] + p0.z);
        s0 += ex2f(xrow[__float_as_int(p1.y)] + p1.x);
        s1 += ex2f(xrow[__float_as_int(p1.w)] + p1.z);
        s0 += ex2f(xrow[__float_as_int(p2.y)] + p2.x);
        s1 += ex2f(xrow[__float_as_int(p2.w)] + p2.z);
        s0 += ex2f(xrow[__float_as_int(p3.y)] + p3.x);
        s1 += ex2f(xrow[__float_as_int(p3.w)] + p3.z);

        outrow[n] = lg2f(s0 + s1) * 0.69314718055994531f;
    }
}

// ---------------------------------------------------------------------------
extern "C" void kernel_launch(void* const* d_in, const int* in_sizes, int n_in,
                              void* d_out, int out_size) {
    const float* x       = (const float*)d_in[0];
    const float* weights = (const float*)d_in[1];
    const int*   idxs    = (const int*)d_in[2];
    float*       out     = (float*)d_out;

    (void)in_sizes; (void)n_in; (void)out_size;

    const int smem_bytes = TB * ROW_STRIDE * sizeof(float);   // 65552 B
    cudaFuncSetAttribute(sum_layer_kernel,
                         cudaFuncAttributeMaxDynamicSharedMemorySize, smem_bytes);

    prep_kernel<<<(N_NODES + 255) / 256, 256>>>(weights, idxs);
    sum_layer_kernel<<<BATCH / TB, THREADS, smem_bytes>>>(x, out);
}

// round 4
// speedup vs baseline: 1.8265x; 1.8265x over previous
#include <cuda_runtime.h>
#include <cstdint>

#define BATCH    8192
#define N_IN     4096
#define N_NODES  2048
#define FAN_IN   8
#define TB       4                 // batch rows per block (SMEM tile, float4-packed)
#define THREADS  256
#define LOG2E    1.4426950408889634f
#define LN2      0.69314718055994531f

// Planar node table: plane i (i=0..3) holds, for node n,
//   (w2_{2i}, idx_{2i} bits, w2_{2i+1}, idx_{2i+1} bits)
// so table loads are fully-coalesced 512B LDG.128s across a warp.
__device__ float4 g_node4[4 * N_NODES];

__device__ __forceinline__ float ex2f(float x) {
    float r; asm("ex2.approx.f32 %0, %1;" : "=f"(r) : "f"(x)); return r;
}
__device__ __forceinline__ float lg2f(float x) {
    float r; asm("lg2.approx.f32 %0, %1;" : "=f"(r) : "f"(x)); return r;
}

// ---------------------------------------------------------------------------
// Prep: fold log_softmax normalizer into weights (pre-scaled by log2e),
// pack planar (w2, idx) pairs. idx arrives as int32 (harness downcast).
// ---------------------------------------------------------------------------
__global__ void prep_kernel(const float* __restrict__ w,
                            const int* __restrict__ idxs) {
    int n = blockIdx.x * blockDim.x + threadIdx.x;
    if (n >= N_NODES) return;
    float wv[FAN_IN];
    float m = -1e30f;
#pragma unroll
    for (int k = 0; k < FAN_IN; k++) {
        wv[k] = w[n * FAN_IN + k];
        m = fmaxf(m, wv[k]);
    }
    float s = 0.0f;
#pragma unroll
    for (int k = 0; k < FAN_IN; k++) s += ex2f((wv[k] - m) * LOG2E);
    float lsew = m + lg2f(s) * LN2;
#pragma unroll
    for (int i = 0; i < 4; i++) {
        float4 p;
        p.x = (wv[2 * i]     - lsew) * LOG2E;
        p.y = __int_as_float(idxs[n * FAN_IN + 2 * i]);
        p.z = (wv[2 * i + 1] - lsew) * LOG2E;
        p.w = __int_as_float(idxs[n * FAN_IN + 2 * i + 1]);
        g_node4[i * N_NODES + n] = p;
    }
}

// ---------------------------------------------------------------------------
// Main: block owns TB=4 batch rows, stored transposed in SMEM:
//   xs4[col] = {x[b0+0][col], .., x[b0+3][col]} * log2e
// One lane per node: each gather is a single LDS.128 serving all 4 rows;
// 4 independent accumulator chains (one per row) give high ILP.
// ---------------------------------------------------------------------------
__global__ void __launch_bounds__(THREADS)
sum_layer_kernel(const float* __restrict__ x, float* __restrict__ out) {
    extern __shared__ float4 xs4[];          // [N_IN], 64 KB
    const int tid = threadIdx.x;
    const int b0  = blockIdx.x * TB;

    // Stage: thread owns column c; 4 coalesced row reads -> 1 conflict-free STS.128.
    const float* xr0 = x + (size_t)b0 * N_IN;
#pragma unroll
    for (int it = 0; it < N_IN / THREADS; it++) {
        int c = it * THREADS + tid;
        float4 v;
        v.x = xr0[0 * N_IN + c] * LOG2E;
        v.y = xr0[1 * N_IN + c] * LOG2E;
        v.z = xr0[2 * N_IN + c] * LOG2E;
        v.w = xr0[3 * N_IN + c] * LOG2E;
        xs4[c] = v;
    }
    __syncthreads();

    const int lane = tid & 31;
    const int w    = tid >> 5;

    // Hoisted output pointers (advance by 256 nodes per chunk).
    float* o0 = out + (size_t)(b0 + 0) * N_NODES + w * 32 + lane;
    float* o1 = out + (size_t)(b0 + 1) * N_NODES + w * 32 + lane;
    float* o2 = out + (size_t)(b0 + 2) * N_NODES + w * 32 + lane;
    float* o3 = out + (size_t)(b0 + 3) * N_NODES + w * 32 + lane;

#define ACC(W2, IDXB, A) do {                                   \
        float4 xv = xs4[__float_as_int(IDXB)];                  \
        A.x += ex2f(xv.x + (W2));                               \
        A.y += ex2f(xv.y + (W2));                               \
        A.z += ex2f(xv.z + (W2));                               \
        A.w += ex2f(xv.w + (W2));                               \
    } while (0)

#pragma unroll
    for (int chunk = 0; chunk < N_NODES / (8 * 32); chunk++) {  // 8 chunks
        int n = chunk * 256 + w * 32 + lane;
        float4 p0 = __ldg(&g_node4[0 * N_NODES + n]);
        float4 p1 = __ldg(&g_node4[1 * N_NODES + n]);
        float4 p2 = __ldg(&g_node4[2 * N_NODES + n]);
        float4 p3 = __ldg(&g_node4[3 * N_NODES + n]);

        float4 a = make_float4(0.f, 0.f, 0.f, 0.f);
        float4 b = make_float4(0.f, 0.f, 0.f, 0.f);
        ACC(p0.x, p0.y, a);  ACC(p0.z, p0.w, b);
        ACC(p1.x, p1.y, a);  ACC(p1.z, p1.w, b);
        ACC(p2.x, p2.y, a);  ACC(p2.z, p2.w, b);
        ACC(p3.x, p3.y, a);  ACC(p3.z, p3.w, b);

        o0[chunk * 256] = lg2f(a.x + b.x) * LN2;
        o1[chunk * 256] = lg2f(a.y + b.y) * LN2;
        o2[chunk * 256] = lg2f(a.z + b.z) * LN2;
        o3[chunk * 256] = lg2f(a.w + b.w) * LN2;
    }
#undef ACC
}

// ---------------------------------------------------------------------------
extern "C" void kernel_launch(void* const* d_in, const int* in_sizes, int n_in,
                              void* d_out, int out_size) {
    const float* x       = (const float*)d_in[0];
    const float* weights = (const float*)d_in[1];
    const int*   idxs    = (const int*)d_in[2];
    float*       out     = (float*)d_out;

    (void)in_sizes; (void)n_in; (void)out_size;

    const int smem_bytes = N_IN * sizeof(float4);   // 65536 B
    cudaFuncSetAttribute(sum_layer_kernel,
                         cudaFuncAttributeMaxDynamicSharedMemorySize, smem_bytes);

    prep_kernel<<<(N_NODES + 255) / 256, 256>>>(weights, idxs);
    sum_layer_kernel<<<BATCH / TB, THREADS, smem_bytes>>>(x, out);
}

// round 5
// speedup vs baseline: 2.0344x; 1.1138x over previous
#include <cuda_runtime.h>
#include <cstdint>

#define BATCH    8192
#define N_IN     4096
#define N_NODES  2048
#define FAN_IN   8
#define TB       4                 // batch rows per block (SMEM tile, float4-packed)
#define THREADS  512
#define LOG2E    1.4426950408889634f
#define LN2      0.69314718055994531f

// Planar node table: plane i (i=0..3) holds, for node n,
//   (w2_{2i}, idx_{2i} bits, w2_{2i+1}, idx_{2i+1} bits)
// so table loads are fully-coalesced 512B LDG.128s across a warp.
__device__ float4 g_node4[4 * N_NODES];

__device__ __forceinline__ float ex2f(float x) {
    float r; asm("ex2.approx.f32 %0, %1;" : "=f"(r) : "f"(x)); return r;
}
__device__ __forceinline__ float lg2f(float x) {
    float r; asm("lg2.approx.f32 %0, %1;" : "=f"(r) : "f"(x)); return r;
}

// ---------------------------------------------------------------------------
// Prep: fold log_softmax normalizer into weights (pre-scaled by log2e),
// pack planar (w2, idx) pairs. idx arrives as int32 (harness downcast).
// ---------------------------------------------------------------------------
__global__ void prep_kernel(const float* __restrict__ w,
                            const int* __restrict__ idxs) {
    int n = blockIdx.x * blockDim.x + threadIdx.x;
    if (n >= N_NODES) return;
    float wv[FAN_IN];
    float m = -1e30f;
#pragma unroll
    for (int k = 0; k < FAN_IN; k++) {
        wv[k] = w[n * FAN_IN + k];
        m = fmaxf(m, wv[k]);
    }
    float s = 0.0f;
#pragma unroll
    for (int k = 0; k < FAN_IN; k++) s += ex2f((wv[k] - m) * LOG2E);
    float lsew = m + lg2f(s) * LN2;
#pragma unroll
    for (int i = 0; i < 4; i++) {
        float4 p;
        p.x = (wv[2 * i]     - lsew) * LOG2E;
        p.y = __int_as_float(idxs[n * FAN_IN + 2 * i]);
        p.z = (wv[2 * i + 1] - lsew) * LOG2E;
        p.w = __int_as_float(idxs[n * FAN_IN + 2 * i + 1]);
        g_node4[i * N_NODES + n] = p;
    }
}

// ---------------------------------------------------------------------------
// Main: block owns TB=4 batch rows, stored transposed in SMEM:
//   xs4[col] = {x[b0+0][col], .., x[b0+3][col]} * log2e
// One lane per node: each gather is a single LDS.128 serving all 4 rows;
// 4 independent accumulator chains (one per row) give high ILP.
// 512 threads/block -> 3 blocks/SM (smem-limited) = 48 warps/SM.
// ---------------------------------------------------------------------------
__global__ void __launch_bounds__(THREADS)
sum_layer_kernel(const float* __restrict__ x, float* __restrict__ out) {
    extern __shared__ float4 xs4[];          // [N_IN], 64 KB
    const int tid = threadIdx.x;
    const int b0  = blockIdx.x * TB;

    // Stage: thread owns column c; 4 coalesced row reads -> 1 conflict-free STS.128.
    const float* xr0 = x + (size_t)b0 * N_IN;
#pragma unroll
    for (int it = 0; it < N_IN / THREADS; it++) {
        int c = it * THREADS + tid;
        float4 v;
        v.x = xr0[0 * N_IN + c] * LOG2E;
        v.y = xr0[1 * N_IN + c] * LOG2E;
        v.z = xr0[2 * N_IN + c] * LOG2E;
        v.w = xr0[3 * N_IN + c] * LOG2E;
        xs4[c] = v;
    }
    __syncthreads();

    // Hoisted output pointers (advance by THREADS nodes per chunk).
    float* o0 = out + (size_t)(b0 + 0) * N_NODES + tid;
    float* o1 = out + (size_t)(b0 + 1) * N_NODES + tid;
    float* o2 = out + (size_t)(b0 + 2) * N_NODES + tid;
    float* o3 = out + (size_t)(b0 + 3) * N_NODES + tid;

#define ACC(W2, IDXB, A) do {                                   \
        float4 xv = xs4[__float_as_int(IDXB)];                  \
        A.x += ex2f(xv.x + (W2));                               \
        A.y += ex2f(xv.y + (W2));                               \
        A.z += ex2f(xv.z + (W2));                               \
        A.w += ex2f(xv.w + (W2));                               \
    } while (0)

#pragma unroll
    for (int chunk = 0; chunk < N_NODES / THREADS; chunk++) {    // 4 chunks
        int n = chunk * THREADS + tid;
        float4 p0 = __ldg(&g_node4[0 * N_NODES + n]);
        float4 p1 = __ldg(&g_node4[1 * N_NODES + n]);
        float4 p2 = __ldg(&g_node4[2 * N_NODES + n]);
        float4 p3 = __ldg(&g_node4[3 * N_NODES + n]);

        float4 a = make_float4(0.f, 0.f, 0.f, 0.f);
        float4 b = make_float4(0.f, 0.f, 0.f, 0.f);
        ACC(p0.x, p0.y, a);  ACC(p0.z, p0.w, b);
        ACC(p1.x, p1.y, a);  ACC(p1.z, p1.w, b);
        ACC(p2.x, p2.y, a);  ACC(p2.z, p2.w, b);
        ACC(p3.x, p3.y, a);  ACC(p3.z, p3.w, b);

        o0[chunk * THREADS] = lg2f(a.x + b.x) * LN2;
        o1[chunk * THREADS] = lg2f(a.y + b.y) * LN2;
        o2[chunk * THREADS] = lg2f(a.z + b.z) * LN2;
        o3[chunk * THREADS] = lg2f(a.w + b.w) * LN2;
    }
#undef ACC
}

// ---------------------------------------------------------------------------
extern "C" void kernel_launch(void* const* d_in, const int* in_sizes, int n_in,
                              void* d_out, int out_size) {
    const float* x       = (const float*)d_in[0];
    const float* weights = (const float*)d_in[1];
    const int*   idxs    = (const int*)d_in[2];
    float*       out     = (float*)d_out;

    (void)in_sizes; (void)n_in; (void)out_size;

    const int smem_bytes = N_IN * sizeof(float4);   // 65536 B
    cudaFuncSetAttribute(sum_layer_kernel,
                         cudaFuncAttributeMaxDynamicSharedMemorySize, smem_bytes);

    prep_kernel<<<(N_NODES + 255) / 256, 256>>>(weights, idxs);
    sum_layer_kernel<<<BATCH / TB, THREADS, smem_bytes>>>(x, out);
}